// round 3
// baseline (speedup 1.0000x reference)
#include <cuda_runtime.h>
#include <math.h>

// Problem constants
#define Dm    1024
#define Sseq  2048
#define Bb    4
#define Hh    16
#define HD    64
#define NT    (Bb * Sseq)   // 8192 tokens

// ---------------- scratch (module-static device memory; no runtime alloc) ---
__device__ float g_xp[NT * Dm];   // x + pe          [token, D]
__device__ float g_q [NT * Dm];   // Q               [bh, s, hd]
__device__ float g_k [NT * Dm];   // K               [bh, s, hd]
__device__ float g_v [NT * Dm];   // V               [bh, s, hd]
__device__ float g_o [NT * Dm];   // attn out        [token, D]
__device__ float g_h [NT * Dm];   // O@wo + bo + xp  [token, D]

// ============================================================================
// Kernel 1: xp = x + pe  (broadcast over batch)
// ============================================================================
__global__ __launch_bounds__(256) void add_pe_kernel(
    const float* __restrict__ x, const float* __restrict__ pe,
    float* __restrict__ xp)
{
    int idx = blockIdx.x * 256 + threadIdx.x;   // float4 index
    int e = idx * 4;
    int t = e >> 10;           // token
    int c = e & 1023;          // channel
    int s = t & (Sseq - 1);    // seq position
    float4 xv = *reinterpret_cast<const float4*>(x + e);
    float4 pv = *reinterpret_cast<const float4*>(pe + s * Dm + c);
    xv.x += pv.x; xv.y += pv.y; xv.z += pv.z; xv.w += pv.w;
    *reinterpret_cast<float4*>(xp + e) = xv;
}

// ============================================================================
// Kernel 2: SGEMM  out[M=8192, N=1024] = A[M,1024] @ W[1024,N] + bias
//   mode 0: scatter to [b, h, s, hd] layout (QKV)
//   mode 1: token-major + residual add
// Tile 128x128x8, 256 threads, 8x8 per-thread microtile.
// ============================================================================
__global__ __launch_bounds__(256) void sgemm_kernel(
    const float* __restrict__ A, const float* __restrict__ W,
    const float* __restrict__ bias, const float* __restrict__ resid,
    float* __restrict__ out, int mode)
{
    __shared__ float As[8][132];   // transposed A tile (padded)
    __shared__ float Bs[8][128];

    int tid = threadIdx.x;
    int tx = tid & 15;
    int ty = tid >> 4;
    int m0 = blockIdx.y * 128;
    int n0 = blockIdx.x * 128;

    int arow = tid >> 1;          // 0..127
    int acol = (tid & 1) * 4;     // 0 or 4
    int brow = tid >> 5;          // 0..7
    int bcol = (tid & 31) * 4;    // 0..124

    const float* Aptr = A + (m0 + arow) * 1024 + acol;
    const float* Wptr = W + brow * 1024 + n0 + bcol;

    float acc[8][8];
#pragma unroll
    for (int i = 0; i < 8; i++)
#pragma unroll
        for (int j = 0; j < 8; j++) acc[i][j] = 0.0f;

    for (int k0 = 0; k0 < 1024; k0 += 8) {
        float4 av = *reinterpret_cast<const float4*>(Aptr + k0);
        float4 bv = *reinterpret_cast<const float4*>(Wptr + (size_t)k0 * 1024);
        As[acol + 0][arow] = av.x;
        As[acol + 1][arow] = av.y;
        As[acol + 2][arow] = av.z;
        As[acol + 3][arow] = av.w;
        *reinterpret_cast<float4*>(&Bs[brow][bcol]) = bv;
        __syncthreads();

#pragma unroll
        for (int kk = 0; kk < 8; kk++) {
            float4 a0 = *reinterpret_cast<const float4*>(&As[kk][ty * 8]);
            float4 a1 = *reinterpret_cast<const float4*>(&As[kk][ty * 8 + 4]);
            float4 b0 = *reinterpret_cast<const float4*>(&Bs[kk][tx * 8]);
            float4 b1 = *reinterpret_cast<const float4*>(&Bs[kk][tx * 8 + 4]);
            float ar[8] = {a0.x, a0.y, a0.z, a0.w, a1.x, a1.y, a1.z, a1.w};
            float br[8] = {b0.x, b0.y, b0.z, b0.w, b1.x, b1.y, b1.z, b1.w};
#pragma unroll
            for (int i = 0; i < 8; i++)
#pragma unroll
                for (int j = 0; j < 8; j++)
                    acc[i][j] = fmaf(ar[i], br[j], acc[i][j]);
        }
        __syncthreads();
    }

    // epilogue
    int mbase = m0 + ty * 8;
    int nbase = n0 + tx * 8;
#pragma unroll
    for (int i = 0; i < 8; i++) {
        int m = mbase + i;
#pragma unroll
        for (int jg = 0; jg < 2; jg++) {
            int n = nbase + jg * 4;
            float4 bval = *reinterpret_cast<const float4*>(bias + n);
            float4 r;
            r.x = acc[i][jg * 4 + 0] + bval.x;
            r.y = acc[i][jg * 4 + 1] + bval.y;
            r.z = acc[i][jg * 4 + 2] + bval.z;
            r.w = acc[i][jg * 4 + 3] + bval.w;
            if (mode == 1) {
                float4 rv = *reinterpret_cast<const float4*>(resid + (size_t)m * Dm + n);
                r.x += rv.x; r.y += rv.y; r.z += rv.z; r.w += rv.w;
                *reinterpret_cast<float4*>(out + (size_t)m * Dm + n) = r;
            } else {
                int h = n >> 6, d = n & 63;
                int b = m >> 11, s = m & (Sseq - 1);
                size_t o = (((size_t)(b * Hh + h) * Sseq) + s) * HD + d;
                *reinterpret_cast<float4*>(out + o) = r;
            }
        }
    }
}

// ============================================================================
// Kernel 3: fused flash attention per (b,h)
//   block = 64-query tile; loops over 32 key tiles of 64.
//   Q,K stored transposed in smem (pad 68) -> conflict-free float4 loads.
//   Ps padded to 65 -> conflict-free broadcast reads in P@V.
// ============================================================================
#define ATTN_SMEM_FLOATS (64*68 + 64*68 + 64*64 + 64*65)

__global__ __launch_bounds__(256) void attn_kernel(
    const float* __restrict__ Q, const float* __restrict__ K,
    const float* __restrict__ V, float* __restrict__ O)
{
    extern __shared__ float sm[];
    float* Qt = sm;               // [64 hd][68]  (scaled by 1/8)
    float* Kt = Qt + 64 * 68;     // [64 hd][68]
    float* Vs = Kt + 64 * 68;     // [64 k ][64]
    float* Ps = Vs + 64 * 64;     // [64 q ][65]

    int tid = threadIdx.x;
    int tx = tid & 15;
    int ty = tid >> 4;
    int bh = blockIdx.y;
    int q0 = blockIdx.x * 64;

    const float* Qb = Q + (size_t)bh * Sseq * HD;
    const float* Kb = K + (size_t)bh * Sseq * HD;
    const float* Vb = V + (size_t)bh * Sseq * HD;

    // load Q tile transposed + scale
    {
        int qrow = tid >> 2;
        int dg = (tid & 3) * 16;
        const float* src = Qb + (size_t)(q0 + qrow) * HD + dg;
#pragma unroll
        for (int ii = 0; ii < 4; ii++) {
            float4 v = *reinterpret_cast<const float4*>(src + ii * 4);
            int d = dg + ii * 4;
            Qt[(d + 0) * 68 + qrow] = v.x * 0.125f;
            Qt[(d + 1) * 68 + qrow] = v.y * 0.125f;
            Qt[(d + 2) * 68 + qrow] = v.z * 0.125f;
            Qt[(d + 3) * 68 + qrow] = v.w * 0.125f;
        }
    }

    float m_i[4], l_i[4], oa[4][4];
#pragma unroll
    for (int i = 0; i < 4; i++) {
        m_i[i] = -1e30f; l_i[i] = 0.0f;
#pragma unroll
        for (int j = 0; j < 4; j++) oa[i][j] = 0.0f;
    }

    for (int kt = 0; kt < Sseq / 64; kt++) {
        int k0 = kt * 64;
        // load K tile transposed
        {
            int krow = tid >> 2;
            int dg = (tid & 3) * 16;
            const float* src = Kb + (size_t)(k0 + krow) * HD + dg;
#pragma unroll
            for (int ii = 0; ii < 4; ii++) {
                float4 v = *reinterpret_cast<const float4*>(src + ii * 4);
                int d = dg + ii * 4;
                Kt[(d + 0) * 68 + krow] = v.x;
                Kt[(d + 1) * 68 + krow] = v.y;
                Kt[(d + 2) * 68 + krow] = v.z;
                Kt[(d + 3) * 68 + krow] = v.w;
            }
        }
        // load V tile direct (natural [k][d])
        {
            const float4* src = reinterpret_cast<const float4*>(Vb + (size_t)k0 * HD);
            float4* dst = reinterpret_cast<float4*>(Vs);
#pragma unroll
            for (int ii = 0; ii < 4; ii++) dst[ii * 256 + tid] = src[ii * 256 + tid];
        }
        __syncthreads();

        // scores: sc[i][j] = sum_d Qt[d][ty*4+i] * Kt[d][tx*4+j]
        float sc[4][4];
#pragma unroll
        for (int i = 0; i < 4; i++)
#pragma unroll
            for (int j = 0; j < 4; j++) sc[i][j] = 0.0f;

#pragma unroll 8
        for (int k = 0; k < 64; k++) {
            float4 qa = *reinterpret_cast<const float4*>(&Qt[k * 68 + ty * 4]);
            float4 kb = *reinterpret_cast<const float4*>(&Kt[k * 68 + tx * 4]);
            float ar[4] = {qa.x, qa.y, qa.z, qa.w};
            float br[4] = {kb.x, kb.y, kb.z, kb.w};
#pragma unroll
            for (int i = 0; i < 4; i++)
#pragma unroll
                for (int j = 0; j < 4; j++)
                    sc[i][j] = fmaf(ar[i], br[j], sc[i][j]);
        }

        // online softmax update (rows owned by same-ty 16-lane group)
#pragma unroll
        for (int i = 0; i < 4; i++) {
            float r = fmaxf(fmaxf(sc[i][0], sc[i][1]), fmaxf(sc[i][2], sc[i][3]));
            r = fmaxf(r, __shfl_xor_sync(0xffffffffu, r, 8));
            r = fmaxf(r, __shfl_xor_sync(0xffffffffu, r, 4));
            r = fmaxf(r, __shfl_xor_sync(0xffffffffu, r, 2));
            r = fmaxf(r, __shfl_xor_sync(0xffffffffu, r, 1));
            float mn = fmaxf(m_i[i], r);
            float corr = __expf(m_i[i] - mn);
            m_i[i] = mn;
            float rs = 0.0f;
#pragma unroll
            for (int j = 0; j < 4; j++) {
                sc[i][j] = __expf(sc[i][j] - mn);
                rs += sc[i][j];
            }
            rs += __shfl_xor_sync(0xffffffffu, rs, 8);
            rs += __shfl_xor_sync(0xffffffffu, rs, 4);
            rs += __shfl_xor_sync(0xffffffffu, rs, 2);
            rs += __shfl_xor_sync(0xffffffffu, rs, 1);
            l_i[i] = l_i[i] * corr + rs;
#pragma unroll
            for (int j = 0; j < 4; j++) oa[i][j] *= corr;
            int q = ty * 4 + i;
            Ps[q * 65 + tx * 4 + 0] = sc[i][0];
            Ps[q * 65 + tx * 4 + 1] = sc[i][1];
            Ps[q * 65 + tx * 4 + 2] = sc[i][2];
            Ps[q * 65 + tx * 4 + 3] = sc[i][3];
        }
        __syncthreads();

        // O += P @ V
#pragma unroll 8
        for (int k = 0; k < 64; k++) {
            float4 vb = *reinterpret_cast<const float4*>(&Vs[k * 64 + tx * 4]);
#pragma unroll
            for (int i = 0; i < 4; i++) {
                float p = Ps[(ty * 4 + i) * 65 + k];
                oa[i][0] = fmaf(p, vb.x, oa[i][0]);
                oa[i][1] = fmaf(p, vb.y, oa[i][1]);
                oa[i][2] = fmaf(p, vb.z, oa[i][2]);
                oa[i][3] = fmaf(p, vb.w, oa[i][3]);
            }
        }
        __syncthreads();
    }

    // epilogue: normalize and store token-major
    int b = bh >> 4, h = bh & 15;
#pragma unroll
    for (int i = 0; i < 4; i++) {
        float inv = 1.0f / l_i[i];
        int tok = b * Sseq + q0 + ty * 4 + i;
        float4 r;
        r.x = oa[i][0] * inv;
        r.y = oa[i][1] * inv;
        r.z = oa[i][2] * inv;
        r.w = oa[i][3] * inv;
        *reinterpret_cast<float4*>(O + (size_t)tok * Dm + h * HD + tx * 4) = r;
    }
}

// ============================================================================
// Kernel 4: LayerNorm per token (two-pass, block=256, 4 floats/thread)
// ============================================================================
__global__ __launch_bounds__(256) void ln_kernel(
    const float* __restrict__ hb, const float* __restrict__ gamma,
    const float* __restrict__ beta, float* __restrict__ out)
{
    int t = blockIdx.x;
    int tid = threadIdx.x;
    __shared__ float red[8];

    float4 v = reinterpret_cast<const float4*>(hb + (size_t)t * Dm)[tid];

    float s = v.x + v.y + v.z + v.w;
    for (int off = 16; off; off >>= 1) s += __shfl_xor_sync(0xffffffffu, s, off);
    if ((tid & 31) == 0) red[tid >> 5] = s;
    __syncthreads();
    float tot = 0.0f;
#pragma unroll
    for (int i = 0; i < 8; i++) tot += red[i];
    float mu = tot * (1.0f / Dm);
    __syncthreads();

    float dx = v.x - mu, dy = v.y - mu, dz = v.z - mu, dw = v.w - mu;
    float sq = dx * dx + dy * dy + dz * dz + dw * dw;
    for (int off = 16; off; off >>= 1) sq += __shfl_xor_sync(0xffffffffu, sq, off);
    if ((tid & 31) == 0) red[tid >> 5] = sq;
    __syncthreads();
    float vtot = 0.0f;
#pragma unroll
    for (int i = 0; i < 8; i++) vtot += red[i];
    float rsd = rsqrtf(vtot * (1.0f / Dm) + 1e-5f);

    int c = tid * 4;
    float4 g = *reinterpret_cast<const float4*>(gamma + c);
    float4 bt = *reinterpret_cast<const float4*>(beta + c);
    float4 r;
    r.x = dx * rsd * g.x + bt.x;
    r.y = dy * rsd * g.y + bt.y;
    r.z = dz * rsd * g.z + bt.z;
    r.w = dw * rsd * g.w + bt.w;
    reinterpret_cast<float4*>(out + (size_t)t * Dm)[tid] = r;
}

// ============================================================================
// launch
// ============================================================================
extern "C" void kernel_launch(void* const* d_in, const int* in_sizes, int n_in,
                              void* d_out, int out_size)
{
    const float* x     = (const float*)d_in[0];
    const float* wq    = (const float*)d_in[1];
    const float* bq    = (const float*)d_in[2];
    const float* wk    = (const float*)d_in[3];
    const float* bk    = (const float*)d_in[4];
    const float* wv    = (const float*)d_in[5];
    const float* bv    = (const float*)d_in[6];
    const float* wo    = (const float*)d_in[7];
    const float* bo    = (const float*)d_in[8];
    const float* gamma = (const float*)d_in[9];
    const float* beta  = (const float*)d_in[10];
    const float* pe    = (const float*)d_in[11];
    float* out = (float*)d_out;

    float *xp, *q, *k, *v, *o, *hb;
    cudaGetSymbolAddress((void**)&xp, g_xp);
    cudaGetSymbolAddress((void**)&q,  g_q);
    cudaGetSymbolAddress((void**)&k,  g_k);
    cudaGetSymbolAddress((void**)&v,  g_v);
    cudaGetSymbolAddress((void**)&o,  g_o);
    cudaGetSymbolAddress((void**)&hb, g_h);

    static const int attn_smem = ATTN_SMEM_FLOATS * 4;
    cudaFuncSetAttribute(attn_kernel, cudaFuncAttributeMaxDynamicSharedMemorySize, attn_smem);

    // 1. x + pe
    add_pe_kernel<<<(NT * Dm) / (256 * 4), 256>>>(x, pe, xp);

    // 2. Q, K, V projections (scatter to head layout)
    dim3 gemm_grid(Dm / 128, NT / 128);   // (8, 64)
    sgemm_kernel<<<gemm_grid, 256>>>(xp, wq, bq, nullptr, q, 0);
    sgemm_kernel<<<gemm_grid, 256>>>(xp, wk, bk, nullptr, k, 0);
    sgemm_kernel<<<gemm_grid, 256>>>(xp, wv, bv, nullptr, v, 0);

    // 3. flash attention
    dim3 attn_grid(Sseq / 64, Bb * Hh);   // (32, 64)
    attn_kernel<<<attn_grid, 256, attn_smem>>>(q, k, v, o);

    // 4. output projection + residual
    sgemm_kernel<<<gemm_grid, 256>>>(o, wo, bo, xp, hb, 1);

    // 5. layernorm
    ln_kernel<<<NT, 256>>>(hb, gamma, beta, out);
}

// round 4
// speedup vs baseline: 2.9819x; 2.9819x over previous
#include <cuda_runtime.h>
#include <math.h>

// Problem constants
#define Dm    1024
#define Sseq  2048
#define Bb    4
#define Hh    16
#define HD    64
#define NT    (Bb * Sseq)   // 8192 tokens

// ---------------- scratch (module-static device memory; no runtime alloc) ---
__device__ float g_xp[NT * Dm];   // x + pe          [token, D]
__device__ float g_q [NT * Dm];   // Q               [bh, s, hd]
__device__ float g_k [NT * Dm];   // K               [bh, s, hd]
__device__ float g_v [NT * Dm];   // V               [bh, s, hd]
__device__ float g_o [NT * Dm];   // attn out        [token, D]
__device__ float g_h [NT * Dm];   // O@wo + bo + xp  [token, D]

// ---------------- tf32 mma helpers -----------------------------------------
__device__ __forceinline__ unsigned f2tf(float f) {
    unsigned r;
    asm("cvt.rna.tf32.f32 %0, %1;" : "=r"(r) : "f"(f));
    return r;
}

__device__ __forceinline__ void mma8(
    float& c0, float& c1, float& c2, float& c3,
    unsigned a0, unsigned a1, unsigned a2, unsigned a3,
    unsigned b0, unsigned b1)
{
    asm volatile(
        "mma.sync.aligned.m16n8k8.row.col.f32.tf32.tf32.f32 "
        "{%0,%1,%2,%3}, {%4,%5,%6,%7}, {%8,%9}, {%0,%1,%2,%3};"
        : "+f"(c0), "+f"(c1), "+f"(c2), "+f"(c3)
        : "r"(a0), "r"(a1), "r"(a2), "r"(a3), "r"(b0), "r"(b1));
}

// ============================================================================
// Kernel 1: xp = x + pe  (broadcast over batch)
// ============================================================================
__global__ __launch_bounds__(256) void add_pe_kernel(
    const float* __restrict__ x, const float* __restrict__ pe,
    float* __restrict__ xp)
{
    int idx = blockIdx.x * 256 + threadIdx.x;   // float4 index
    int e = idx * 4;
    int t = e >> 10;           // token
    int c = e & 1023;          // channel
    int s = t & (Sseq - 1);    // seq position
    float4 xv = *reinterpret_cast<const float4*>(x + e);
    float4 pv = *reinterpret_cast<const float4*>(pe + s * Dm + c);
    xv.x += pv.x; xv.y += pv.y; xv.z += pv.z; xv.w += pv.w;
    *reinterpret_cast<float4*>(xp + e) = xv;
}

// ============================================================================
// Kernel 2: tf32 tensor-core GEMM  out[8192,1024] = A @ W + bias
//   Tile 128x128xKc32, 256 threads = 8 warps, warp tile 64x32 (4x4 m16n8).
//   smem pads: As ld 36 (== 4 mod 32), Bs ld 136 (== 8 mod 32) ->
//   all fragment LDS are bank-conflict-free.
//   mode 0: scatter to [b,h,s,hd]; mode 1: token-major + residual.
// ============================================================================
__global__ __launch_bounds__(256, 2) void gemm_tc(
    const float* __restrict__ A, const float* __restrict__ W,
    const float* __restrict__ bias, const float* __restrict__ resid,
    float* __restrict__ out, int mode)
{
    __shared__ float As[128][36];
    __shared__ float Bs[32][136];

    int tid  = threadIdx.x;
    int lane = tid & 31;
    int warp = tid >> 5;
    int g    = lane >> 2;      // group (row within fragment)
    int tig  = lane & 3;       // thread-in-group
    int wm   = warp & 1;       // 0..1 -> 64 rows each
    int wn   = warp >> 1;      // 0..3 -> 32 cols each
    int m0   = blockIdx.y * 128;
    int n0   = blockIdx.x * 128;

    float acc[4][4][4];
#pragma unroll
    for (int i = 0; i < 4; i++)
#pragma unroll
        for (int j = 0; j < 4; j++)
#pragma unroll
            for (int r = 0; r < 4; r++) acc[i][j][r] = 0.0f;

    for (int k0 = 0; k0 < 1024; k0 += 32) {
        // fill A tile 128x32 (coalesced 128B rows)
#pragma unroll
        for (int i = 0; i < 4; i++) {
            int f = tid + 256 * i;          // float4 id
            int row = f >> 3, c4 = f & 7;
            float4 v = *reinterpret_cast<const float4*>(
                A + (size_t)(m0 + row) * 1024 + k0 + c4 * 4);
            *reinterpret_cast<float4*>(&As[row][c4 * 4]) = v;
        }
        // fill B tile 32x128
#pragma unroll
        for (int i = 0; i < 4; i++) {
            int f = tid + 256 * i;
            int row = f >> 5, c4 = f & 31;
            float4 v = *reinterpret_cast<const float4*>(
                W + (size_t)(k0 + row) * 1024 + n0 + c4 * 4);
            *reinterpret_cast<float4*>(&Bs[row][c4 * 4]) = v;
        }
        __syncthreads();

#pragma unroll
        for (int ks = 0; ks < 4; ks++) {
            int k = ks * 8;
            unsigned a[4][4], b[4][2];
#pragma unroll
            for (int mt = 0; mt < 4; mt++) {
                int r = wm * 64 + mt * 16 + g;
                a[mt][0] = f2tf(As[r    ][k + tig]);
                a[mt][1] = f2tf(As[r + 8][k + tig]);
                a[mt][2] = f2tf(As[r    ][k + tig + 4]);
                a[mt][3] = f2tf(As[r + 8][k + tig + 4]);
            }
#pragma unroll
            for (int nt = 0; nt < 4; nt++) {
                int c = wn * 32 + nt * 8 + g;
                b[nt][0] = f2tf(Bs[k + tig    ][c]);
                b[nt][1] = f2tf(Bs[k + tig + 4][c]);
            }
#pragma unroll
            for (int mt = 0; mt < 4; mt++)
#pragma unroll
                for (int nt = 0; nt < 4; nt++)
                    mma8(acc[mt][nt][0], acc[mt][nt][1], acc[mt][nt][2], acc[mt][nt][3],
                         a[mt][0], a[mt][1], a[mt][2], a[mt][3],
                         b[nt][0], b[nt][1]);
        }
        __syncthreads();
    }

    // epilogue
#pragma unroll
    for (int mt = 0; mt < 4; mt++) {
        int r0 = m0 + wm * 64 + mt * 16 + g;
#pragma unroll
        for (int nt = 0; nt < 4; nt++) {
            int c = n0 + wn * 32 + nt * 8 + 2 * tig;
            float2 bv = *reinterpret_cast<const float2*>(bias + c);
            float2 lo = make_float2(acc[mt][nt][0] + bv.x, acc[mt][nt][1] + bv.y);
            float2 hi = make_float2(acc[mt][nt][2] + bv.x, acc[mt][nt][3] + bv.y);
            if (mode == 1) {
                float2 rl = *reinterpret_cast<const float2*>(resid + (size_t)r0 * Dm + c);
                float2 rh = *reinterpret_cast<const float2*>(resid + (size_t)(r0 + 8) * Dm + c);
                lo.x += rl.x; lo.y += rl.y;
                hi.x += rh.x; hi.y += rh.y;
                *reinterpret_cast<float2*>(out + (size_t)r0 * Dm + c) = lo;
                *reinterpret_cast<float2*>(out + (size_t)(r0 + 8) * Dm + c) = hi;
            } else {
                int h = c >> 6, d = c & 63;
                int b0 = r0 >> 11, s0 = r0 & (Sseq - 1);
                size_t o0 = (((size_t)(b0 * Hh + h) * Sseq) + s0) * HD + d;
                size_t o1 = o0 + 8 * HD;   // row+8 same (b,h), s+8
                *reinterpret_cast<float2*>(out + o0) = lo;
                *reinterpret_cast<float2*>(out + o1) = hi;
            }
        }
    }
}

// ============================================================================
// Kernel 3: flash attention, tf32 mma. 128-query x 64-key tiles.
//   8 warps; warp w owns query rows [w*16, w*16+16) -> softmax warp-local.
//   smem pads chosen so all fragment LDS are conflict-free:
//     Qs/Ks/Ps ld 68 (==4 mod 32), Vs ld 72 (==8 mod 32).
// ============================================================================
#define ATTN_SMEM_FLOATS (128*68 + 64*68 + 64*72 + 128*68)

__global__ __launch_bounds__(256, 2) void attn_tc(
    const float* __restrict__ Q, const float* __restrict__ K,
    const float* __restrict__ V, float* __restrict__ O)
{
    extern __shared__ float sm[];
    float* Qs = sm;                 // [128][68]
    float* Ks = Qs + 128 * 68;      // [64][68]
    float* Vs = Ks + 64 * 68;       // [64][72]
    float* Ps = Vs + 64 * 72;       // [128][68]

    int tid  = threadIdx.x;
    int lane = tid & 31;
    int warp = tid >> 5;
    int g    = lane >> 2;
    int tig  = lane & 3;
    int bh   = blockIdx.y;
    int q0   = blockIdx.x * 128;
    int qrow = warp * 16 + g;       // this thread's base row in the tile

    const float* Qb = Q + (size_t)bh * Sseq * HD;
    const float* Kb = K + (size_t)bh * Sseq * HD;
    const float* Vb = V + (size_t)bh * Sseq * HD;

    // stage Q tile (scaled by 1/sqrt(64))
#pragma unroll
    for (int i = 0; i < 8; i++) {
        int f = tid + 256 * i;        // float4 id (2048 total)
        int row = f >> 4, c4 = f & 15;
        float4 v = *reinterpret_cast<const float4*>(Qb + (size_t)(q0 + row) * HD + c4 * 4);
        v.x *= 0.125f; v.y *= 0.125f; v.z *= 0.125f; v.w *= 0.125f;
        *reinterpret_cast<float4*>(&Qs[row * 68 + c4 * 4]) = v;
    }

    float m0r = -1e30f, m1r = -1e30f, l0 = 0.0f, l1 = 0.0f;
    float o[8][4];
#pragma unroll
    for (int i = 0; i < 8; i++)
#pragma unroll
        for (int j = 0; j < 4; j++) o[i][j] = 0.0f;

    for (int kt = 0; kt < Sseq / 64; kt++) {
        int k0 = kt * 64;
        // stage K and V tiles (64x64 each)
#pragma unroll
        for (int i = 0; i < 4; i++) {
            int f = tid + 256 * i;
            int row = f >> 4, c4 = f & 15;
            float4 kv = *reinterpret_cast<const float4*>(Kb + (size_t)(k0 + row) * HD + c4 * 4);
            *reinterpret_cast<float4*>(&Ks[row * 68 + c4 * 4]) = kv;
            float4 vv = *reinterpret_cast<const float4*>(Vb + (size_t)(k0 + row) * HD + c4 * 4);
            *reinterpret_cast<float4*>(&Vs[row * 72 + c4 * 4]) = vv;
        }
        __syncthreads();

        // S = Q @ K^T : warp computes 16x64
        float s[8][4];
#pragma unroll
        for (int nt = 0; nt < 8; nt++)
#pragma unroll
            for (int j = 0; j < 4; j++) s[nt][j] = 0.0f;

#pragma unroll
        for (int kk = 0; kk < 8; kk++) {
            int kc = kk * 8;
            unsigned a0 = f2tf(Qs[(qrow    ) * 68 + kc + tig]);
            unsigned a1 = f2tf(Qs[(qrow + 8) * 68 + kc + tig]);
            unsigned a2 = f2tf(Qs[(qrow    ) * 68 + kc + tig + 4]);
            unsigned a3 = f2tf(Qs[(qrow + 8) * 68 + kc + tig + 4]);
#pragma unroll
            for (int nt = 0; nt < 8; nt++) {
                unsigned b0 = f2tf(Ks[(nt * 8 + g) * 68 + kc + tig]);
                unsigned b1 = f2tf(Ks[(nt * 8 + g) * 68 + kc + tig + 4]);
                mma8(s[nt][0], s[nt][1], s[nt][2], s[nt][3], a0, a1, a2, a3, b0, b1);
            }
        }

        // online softmax (rows g and g+8, warp-local over the 4-lane quad)
        float rmax0 = -1e30f, rmax1 = -1e30f;
#pragma unroll
        for (int nt = 0; nt < 8; nt++) {
            rmax0 = fmaxf(rmax0, fmaxf(s[nt][0], s[nt][1]));
            rmax1 = fmaxf(rmax1, fmaxf(s[nt][2], s[nt][3]));
        }
        rmax0 = fmaxf(rmax0, __shfl_xor_sync(0xffffffffu, rmax0, 1));
        rmax0 = fmaxf(rmax0, __shfl_xor_sync(0xffffffffu, rmax0, 2));
        rmax1 = fmaxf(rmax1, __shfl_xor_sync(0xffffffffu, rmax1, 1));
        rmax1 = fmaxf(rmax1, __shfl_xor_sync(0xffffffffu, rmax1, 2));
        float mn0 = fmaxf(m0r, rmax0), mn1 = fmaxf(m1r, rmax1);
        float cf0 = __expf(m0r - mn0), cf1 = __expf(m1r - mn1);
        m0r = mn0; m1r = mn1;
        float rs0 = 0.0f, rs1 = 0.0f;
#pragma unroll
        for (int nt = 0; nt < 8; nt++) {
            s[nt][0] = __expf(s[nt][0] - mn0);
            s[nt][1] = __expf(s[nt][1] - mn0);
            s[nt][2] = __expf(s[nt][2] - mn1);
            s[nt][3] = __expf(s[nt][3] - mn1);
            rs0 += s[nt][0] + s[nt][1];
            rs1 += s[nt][2] + s[nt][3];
        }
        rs0 += __shfl_xor_sync(0xffffffffu, rs0, 1);
        rs0 += __shfl_xor_sync(0xffffffffu, rs0, 2);
        rs1 += __shfl_xor_sync(0xffffffffu, rs1, 1);
        rs1 += __shfl_xor_sync(0xffffffffu, rs1, 2);
        l0 = l0 * cf0 + rs0;
        l1 = l1 * cf1 + rs1;
#pragma unroll
        for (int ht = 0; ht < 8; ht++) {
            o[ht][0] *= cf0; o[ht][1] *= cf0;
            o[ht][2] *= cf1; o[ht][3] *= cf1;
        }
        // park P in smem (each warp touches only its own 16 rows)
#pragma unroll
        for (int nt = 0; nt < 8; nt++) {
            *reinterpret_cast<float2*>(&Ps[(qrow    ) * 68 + nt * 8 + 2 * tig]) =
                make_float2(s[nt][0], s[nt][1]);
            *reinterpret_cast<float2*>(&Ps[(qrow + 8) * 68 + nt * 8 + 2 * tig]) =
                make_float2(s[nt][2], s[nt][3]);
        }
        __syncwarp();

        // O += P @ V
#pragma unroll
        for (int kk = 0; kk < 8; kk++) {
            int kc = kk * 8;
            unsigned a0 = f2tf(Ps[(qrow    ) * 68 + kc + tig]);
            unsigned a1 = f2tf(Ps[(qrow + 8) * 68 + kc + tig]);
            unsigned a2 = f2tf(Ps[(qrow    ) * 68 + kc + tig + 4]);
            unsigned a3 = f2tf(Ps[(qrow + 8) * 68 + kc + tig + 4]);
#pragma unroll
            for (int ht = 0; ht < 8; ht++) {
                unsigned b0 = f2tf(Vs[(kc + tig    ) * 72 + ht * 8 + g]);
                unsigned b1 = f2tf(Vs[(kc + tig + 4) * 72 + ht * 8 + g]);
                mma8(o[ht][0], o[ht][1], o[ht][2], o[ht][3], a0, a1, a2, a3, b0, b1);
            }
        }
        __syncthreads();
    }

    // epilogue: normalize, store token-major into [tok][1024]
    int b = bh >> 4, h = bh & 15;
    int tok0 = b * Sseq + q0 + qrow;
    float inv0 = 1.0f / l0, inv1 = 1.0f / l1;
#pragma unroll
    for (int ht = 0; ht < 8; ht++) {
        int col = h * HD + ht * 8 + 2 * tig;
        *reinterpret_cast<float2*>(O + (size_t)tok0 * Dm + col) =
            make_float2(o[ht][0] * inv0, o[ht][1] * inv0);
        *reinterpret_cast<float2*>(O + (size_t)(tok0 + 8) * Dm + col) =
            make_float2(o[ht][2] * inv1, o[ht][3] * inv1);
    }
}

// ============================================================================
// Kernel 4: LayerNorm per token (block=256, 4 floats/thread)
// ============================================================================
__global__ __launch_bounds__(256) void ln_kernel(
    const float* __restrict__ hb, const float* __restrict__ gamma,
    const float* __restrict__ beta, float* __restrict__ out)
{
    int t = blockIdx.x;
    int tid = threadIdx.x;
    __shared__ float red[8];

    float4 v = reinterpret_cast<const float4*>(hb + (size_t)t * Dm)[tid];

    float s = v.x + v.y + v.z + v.w;
    for (int off = 16; off; off >>= 1) s += __shfl_xor_sync(0xffffffffu, s, off);
    if ((tid & 31) == 0) red[tid >> 5] = s;
    __syncthreads();
    float tot = 0.0f;
#pragma unroll
    for (int i = 0; i < 8; i++) tot += red[i];
    float mu = tot * (1.0f / Dm);
    __syncthreads();

    float dx = v.x - mu, dy = v.y - mu, dz = v.z - mu, dw = v.w - mu;
    float sq = dx * dx + dy * dy + dz * dz + dw * dw;
    for (int off = 16; off; off >>= 1) sq += __shfl_xor_sync(0xffffffffu, sq, off);
    if ((tid & 31) == 0) red[tid >> 5] = sq;
    __syncthreads();
    float vtot = 0.0f;
#pragma unroll
    for (int i = 0; i < 8; i++) vtot += red[i];
    float rsd = rsqrtf(vtot * (1.0f / Dm) + 1e-5f);

    int c = tid * 4;
    float4 gm = *reinterpret_cast<const float4*>(gamma + c);
    float4 bt = *reinterpret_cast<const float4*>(beta + c);
    float4 r;
    r.x = dx * rsd * gm.x + bt.x;
    r.y = dy * rsd * gm.y + bt.y;
    r.z = dz * rsd * gm.z + bt.z;
    r.w = dw * rsd * gm.w + bt.w;
    reinterpret_cast<float4*>(out + (size_t)t * Dm)[tid] = r;
}

// ============================================================================
// launch
// ============================================================================
extern "C" void kernel_launch(void* const* d_in, const int* in_sizes, int n_in,
                              void* d_out, int out_size)
{
    const float* x     = (const float*)d_in[0];
    const float* wq    = (const float*)d_in[1];
    const float* bq    = (const float*)d_in[2];
    const float* wk    = (const float*)d_in[3];
    const float* bk    = (const float*)d_in[4];
    const float* wv    = (const float*)d_in[5];
    const float* bv    = (const float*)d_in[6];
    const float* wo    = (const float*)d_in[7];
    const float* bo    = (const float*)d_in[8];
    const float* gamma = (const float*)d_in[9];
    const float* beta  = (const float*)d_in[10];
    const float* pe    = (const float*)d_in[11];
    float* out = (float*)d_out;

    float *xp, *q, *k, *v, *o, *hb;
    cudaGetSymbolAddress((void**)&xp, g_xp);
    cudaGetSymbolAddress((void**)&q,  g_q);
    cudaGetSymbolAddress((void**)&k,  g_k);
    cudaGetSymbolAddress((void**)&v,  g_v);
    cudaGetSymbolAddress((void**)&o,  g_o);
    cudaGetSymbolAddress((void**)&hb, g_h);

    static const int attn_smem = ATTN_SMEM_FLOATS * 4;
    cudaFuncSetAttribute(attn_tc, cudaFuncAttributeMaxDynamicSharedMemorySize, attn_smem);

    // 1. x + pe
    add_pe_kernel<<<(NT * Dm) / (256 * 4), 256>>>(x, pe, xp);

    // 2. Q, K, V projections (scatter to head layout)
    dim3 gemm_grid(Dm / 128, NT / 128);   // (8, 64)
    gemm_tc<<<gemm_grid, 256>>>(xp, wq, bq, nullptr, q, 0);
    gemm_tc<<<gemm_grid, 256>>>(xp, wk, bk, nullptr, k, 0);
    gemm_tc<<<gemm_grid, 256>>>(xp, wv, bv, nullptr, v, 0);

    // 3. flash attention
    dim3 attn_grid(Sseq / 128, Bb * Hh);  // (16, 64)
    attn_tc<<<attn_grid, 256, attn_smem>>>(q, k, v, o);

    // 4. output projection + residual
    gemm_tc<<<gemm_grid, 256>>>(o, wo, bo, xp, hb, 1);

    // 5. layernorm
    ln_kernel<<<NT, 256>>>(hb, gamma, beta, out);
}